// round 8
// baseline (speedup 1.0000x reference)
#include <cuda_runtime.h>

#define N_NODES 50000
#define N_EDGES 800000
#define SCAN_NB ((N_NODES + 255) / 256)   // 196 blocks

// ---- scratch (allocation-free: __device__ globals) ----
__device__ float g_deg  [N_NODES];
__device__ float g_dinv [N_NODES];
__device__ int   g_cnt  [N_NODES];
__device__ int   g_off  [N_NODES + 1];
__device__ int   g_cur  [N_NODES];
__device__ int   g_srow [N_EDGES];
__device__ float g_snorm[N_EDGES];
__device__ float g_t  [N_NODES * 64];
__device__ float g_h  [N_NODES * 64];
__device__ float g_h2 [N_NODES * 64];
// lookback-scan state
__device__ int   g_ticket;
__device__ int   g_flag [SCAN_NB];   // 0=invalid 1=aggregate 2=prefix
__device__ int   g_aggr [SCAN_NB];
__device__ int   g_pref [SCAN_NB];

// ---------------------------------------------------------------------------
__global__ void zero_kernel() {
    int n = blockIdx.x * blockDim.x + threadIdx.x;
    if (n < N_NODES) { g_deg[n] = 0.0f; g_cnt[n] = 0; }
    if (n < SCAN_NB) g_flag[n] = 0;
    if (n == 0) g_ticket = 0;
}

__global__ void hist_kernel(const int* __restrict__ row, const int* __restrict__ col) {
    int e = blockIdx.x * blockDim.x + threadIdx.x;
    if (e < N_EDGES) {
        atomicAdd(&g_deg[row[e]], 1.0f);
        atomicAdd(&g_cnt[col[e]], 1);
    }
}

// ---------------------------------------------------------------------------
// block-wide exclusive scan over 256 values; also returns block total
__device__ __forceinline__ int block_excl_scan_256(int v, int tid, int* total) {
    int lane = tid & 31, wid = tid >> 5;
    int x = v;
#pragma unroll
    for (int d = 1; d < 32; d <<= 1) {
        int y = __shfl_up_sync(0xFFFFFFFFu, x, d);
        if (lane >= d) x += y;
    }
    __shared__ int wsum[8];
    if (lane == 31) wsum[wid] = x;
    __syncthreads();
    if (wid == 0) {
        int w = (lane < 8) ? wsum[lane] : 0;
#pragma unroll
        for (int d = 1; d < 8; d <<= 1) {
            int y = __shfl_up_sync(0xFFFFFFFFu, w, d);
            if (lane >= d) w += y;
        }
        if (lane < 8) wsum[lane] = w;
    }
    __syncthreads();
    int incl = x + (wid > 0 ? wsum[wid - 1] : 0);
    *total = wsum[7];              // inclusive sum of all 8 warps
    __syncthreads();
    return incl - v;
}

// single-pass decoupled-lookback scan of g_cnt -> g_off/g_cur (+ dinv fold-in)
__global__ void scan_lookback_kernel() {
    __shared__ int sbid, s_prefix;
    int tid = threadIdx.x;
    if (tid == 0) sbid = atomicAdd(&g_ticket, 1);   // enforce ascending order
    __syncthreads();
    const int b = sbid;
    const int i = b * 256 + tid;

    int v = (i < N_NODES) ? g_cnt[i] : 0;
    int total;
    int excl = block_excl_scan_256(v, tid, &total);

    if (tid == 0) {
        if (b == 0) {
            g_pref[0] = total;
            __threadfence();
            atomicExch(&g_flag[0], 2);
            s_prefix = 0;
        } else {
            g_aggr[b] = total;
            __threadfence();
            atomicExch(&g_flag[b], 1);
            // lookback
            int run = 0, j = b - 1;
            while (true) {
                int f;
                do { f = atomicOr(&g_flag[j], 0); } while (f == 0);
                __threadfence();
                if (f == 2) { run += *(volatile int*)&g_pref[j]; break; }
                run += *(volatile int*)&g_aggr[j];
                j--;
            }
            g_pref[b] = run + total;
            __threadfence();
            atomicExch(&g_flag[b], 2);
            s_prefix = run;
        }
    }
    __syncthreads();

    if (i < N_NODES) {
        int o = s_prefix + excl;
        g_off[i] = o;
        g_cur[i] = o;
        float d = g_deg[i];
        g_dinv[i] = (d > 0.0f) ? rsqrtf(d) : 0.0f;
    }
    if (i == 0) g_off[N_NODES] = N_EDGES;
}

__global__ void build_kernel(const int* __restrict__ row, const int* __restrict__ col) {
    int e = blockIdx.x * blockDim.x + threadIdx.x;
    if (e < N_EDGES) {
        int r = row[e], c = col[e];
        int p = atomicAdd(&g_cur[c], 1);
        g_srow[p]  = r;
        g_snorm[p] = g_dinv[r] * g_dinv[c];
    }
}

// ---------------------------------------------------------------------------
// Fused dual GEMM: T = A @ Wa,  H = A @ Wb + bias   (A: [N,64], W: [64,64])
__global__ void dual_gemm_kernel(const float* __restrict__ A,
                                 const float* __restrict__ Wa,
                                 const float* __restrict__ Wb,
                                 const float* __restrict__ bias,
                                 float* __restrict__ T,
                                 float* __restrict__ H) {
    __shared__ float xs[64][65];
    const int tid  = threadIdx.x;
    const int row0 = blockIdx.x * 64;

    for (int i = tid; i < 64 * 16; i += 256) {
        int r = i >> 4, c4 = i & 15;
        float4 v = make_float4(0.f, 0.f, 0.f, 0.f);
        int gr = row0 + r;
        if (gr < N_NODES) v = __ldg(reinterpret_cast<const float4*>(A) + gr * 16 + c4);
        xs[r][c4 * 4 + 0] = v.x; xs[r][c4 * 4 + 1] = v.y;
        xs[r][c4 * 4 + 2] = v.z; xs[r][c4 * 4 + 3] = v.w;
    }
    __syncthreads();

    const int tr = tid >> 4, tc = tid & 15;
    const int r0 = tr * 4, c0 = tc * 4;

    float accA[4][4], accB[4][4];
#pragma unroll
    for (int i = 0; i < 4; i++)
#pragma unroll
        for (int j = 0; j < 4; j++) { accA[i][j] = 0.f; accB[i][j] = 0.f; }

#pragma unroll 8
    for (int k = 0; k < 64; k++) {
        float4 wa = __ldg(reinterpret_cast<const float4*>(Wa + k * 64 + c0));
        float4 wb = __ldg(reinterpret_cast<const float4*>(Wb + k * 64 + c0));
        float x0 = xs[r0 + 0][k];
        float x1 = xs[r0 + 1][k];
        float x2 = xs[r0 + 2][k];
        float x3 = xs[r0 + 3][k];
        accA[0][0] = fmaf(x0, wa.x, accA[0][0]); accA[0][1] = fmaf(x0, wa.y, accA[0][1]);
        accA[0][2] = fmaf(x0, wa.z, accA[0][2]); accA[0][3] = fmaf(x0, wa.w, accA[0][3]);
        accA[1][0] = fmaf(x1, wa.x, accA[1][0]); accA[1][1] = fmaf(x1, wa.y, accA[1][1]);
        accA[1][2] = fmaf(x1, wa.z, accA[1][2]); accA[1][3] = fmaf(x1, wa.w, accA[1][3]);
        accA[2][0] = fmaf(x2, wa.x, accA[2][0]); accA[2][1] = fmaf(x2, wa.y, accA[2][1]);
        accA[2][2] = fmaf(x2, wa.z, accA[2][2]); accA[2][3] = fmaf(x2, wa.w, accA[2][3]);
        accA[3][0] = fmaf(x3, wa.x, accA[3][0]); accA[3][1] = fmaf(x3, wa.y, accA[3][1]);
        accA[3][2] = fmaf(x3, wa.z, accA[3][2]); accA[3][3] = fmaf(x3, wa.w, accA[3][3]);
        accB[0][0] = fmaf(x0, wb.x, accB[0][0]); accB[0][1] = fmaf(x0, wb.y, accB[0][1]);
        accB[0][2] = fmaf(x0, wb.z, accB[0][2]); accB[0][3] = fmaf(x0, wb.w, accB[0][3]);
        accB[1][0] = fmaf(x1, wb.x, accB[1][0]); accB[1][1] = fmaf(x1, wb.y, accB[1][1]);
        accB[1][2] = fmaf(x1, wb.z, accB[1][2]); accB[1][3] = fmaf(x1, wb.w, accB[1][3]);
        accB[2][0] = fmaf(x2, wb.x, accB[2][0]); accB[2][1] = fmaf(x2, wb.y, accB[2][1]);
        accB[2][2] = fmaf(x2, wb.z, accB[2][2]); accB[2][3] = fmaf(x2, wb.w, accB[2][3]);
        accB[3][0] = fmaf(x3, wb.x, accB[3][0]); accB[3][1] = fmaf(x3, wb.y, accB[3][1]);
        accB[3][2] = fmaf(x3, wb.z, accB[3][2]); accB[3][3] = fmaf(x3, wb.w, accB[3][3]);
    }

    float4 bv = __ldg(reinterpret_cast<const float4*>(bias + c0));

#pragma unroll
    for (int i = 0; i < 4; i++) {
        int gr = row0 + r0 + i;
        if (gr < N_NODES) {
            float4 oa = make_float4(accA[i][0], accA[i][1], accA[i][2], accA[i][3]);
            float4 ob = make_float4(accB[i][0] + bv.x, accB[i][1] + bv.y,
                                    accB[i][2] + bv.z, accB[i][3] + bv.w);
            *reinterpret_cast<float4*>(T + gr * 64 + c0) = oa;
            *reinterpret_cast<float4*>(H + gr * 64 + c0) = ob;
        }
    }
}

// Output GEMM: C[N,32] = A[N,64] @ W[64,32] + b. 64-row tile, 128 threads.
__global__ void out_gemm_kernel(const float* __restrict__ A,
                                const float* __restrict__ W,
                                const float* __restrict__ bias,
                                float* __restrict__ C) {
    __shared__ float xs[64][65];
    const int tid  = threadIdx.x;
    const int row0 = blockIdx.x * 64;

    for (int i = tid; i < 64 * 16; i += 128) {
        int r = i >> 4, c4 = i & 15;
        float4 v = make_float4(0.f, 0.f, 0.f, 0.f);
        int gr = row0 + r;
        if (gr < N_NODES) v = __ldg(reinterpret_cast<const float4*>(A) + gr * 16 + c4);
        xs[r][c4 * 4 + 0] = v.x; xs[r][c4 * 4 + 1] = v.y;
        xs[r][c4 * 4 + 2] = v.z; xs[r][c4 * 4 + 3] = v.w;
    }
    __syncthreads();

    const int tr = tid >> 3, tc = tid & 7;
    const int r0 = tr * 4, c0 = tc * 4;

    float acc[4][4];
#pragma unroll
    for (int i = 0; i < 4; i++)
#pragma unroll
        for (int j = 0; j < 4; j++) acc[i][j] = 0.f;

#pragma unroll 8
    for (int k = 0; k < 64; k++) {
        float4 wv = __ldg(reinterpret_cast<const float4*>(W + k * 32 + c0));
        float x0 = xs[r0 + 0][k];
        float x1 = xs[r0 + 1][k];
        float x2 = xs[r0 + 2][k];
        float x3 = xs[r0 + 3][k];
        acc[0][0] = fmaf(x0, wv.x, acc[0][0]); acc[0][1] = fmaf(x0, wv.y, acc[0][1]);
        acc[0][2] = fmaf(x0, wv.z, acc[0][2]); acc[0][3] = fmaf(x0, wv.w, acc[0][3]);
        acc[1][0] = fmaf(x1, wv.x, acc[1][0]); acc[1][1] = fmaf(x1, wv.y, acc[1][1]);
        acc[1][2] = fmaf(x1, wv.z, acc[1][2]); acc[1][3] = fmaf(x1, wv.w, acc[1][3]);
        acc[2][0] = fmaf(x2, wv.x, acc[2][0]); acc[2][1] = fmaf(x2, wv.y, acc[2][1]);
        acc[2][2] = fmaf(x2, wv.z, acc[2][2]); acc[2][3] = fmaf(x2, wv.w, acc[2][3]);
        acc[3][0] = fmaf(x3, wv.x, acc[3][0]); acc[3][1] = fmaf(x3, wv.y, acc[3][1]);
        acc[3][2] = fmaf(x3, wv.z, acc[3][2]); acc[3][3] = fmaf(x3, wv.w, acc[3][3]);
    }

    float4 bv = __ldg(reinterpret_cast<const float4*>(bias + c0));
#pragma unroll
    for (int i = 0; i < 4; i++) {
        int gr = row0 + r0 + i;
        if (gr < N_NODES) {
            float4 o = make_float4(acc[i][0] + bv.x, acc[i][1] + bv.y,
                                   acc[i][2] + bv.z, acc[i][3] + bv.w);
            *reinterpret_cast<float4*>(C + gr * 32 + c0) = o;
        }
    }
}

// ---------------------------------------------------------------------------
// CSR aggregation + ReLU: 16 threads per node, float4 column chunk each.
__global__ void agg_kernel(const float* __restrict__ t, float* __restrict__ h) {
    int gid  = blockIdx.x * blockDim.x + threadIdx.x;
    int node = gid >> 4;
    if (node >= N_NODES) return;
    int c4 = gid & 15;

    int s = g_off[node];
    int e = g_off[node + 1];

    float4 acc = *reinterpret_cast<const float4*>(h + node * 64 + c4 * 4);

    for (int j = s; j < e; j++) {
        int   r  = __ldg(&g_srow[j]);
        float nv = __ldg(&g_snorm[j]);
        float4 v = __ldg(reinterpret_cast<const float4*>(t + r * 64) + c4);
        acc.x = fmaf(v.x, nv, acc.x);
        acc.y = fmaf(v.y, nv, acc.y);
        acc.z = fmaf(v.z, nv, acc.z);
        acc.w = fmaf(v.w, nv, acc.w);
    }

    acc.x = fmaxf(acc.x, 0.f);
    acc.y = fmaxf(acc.y, 0.f);
    acc.z = fmaxf(acc.z, 0.f);
    acc.w = fmaxf(acc.w, 0.f);
    *reinterpret_cast<float4*>(h + node * 64 + c4 * 4) = acc;
}

// ---------------------------------------------------------------------------
extern "C" void kernel_launch(void* const* d_in, const int* in_sizes, int n_in,
                              void* d_out, int out_size) {
    const float* x      = (const float*)d_in[0];
    const int*   ei     = (const int*)d_in[1];
    const int*   row    = ei;
    const int*   col    = ei + N_EDGES;
    const float* W_in1  = (const float*)d_in[2];
    const float* W_nb1  = (const float*)d_in[3];
    const float* b1     = (const float*)d_in[4];
    const float* W_in2  = (const float*)d_in[5];
    const float* W_nb2  = (const float*)d_in[6];
    const float* b2     = (const float*)d_in[7];
    const float* W_out  = (const float*)d_in[8];
    const float* b_out  = (const float*)d_in[9];
    float*       out    = (float*)d_out;

    float *t_p, *h_p, *h2_p;
    cudaGetSymbolAddress((void**)&t_p,  g_t);
    cudaGetSymbolAddress((void**)&h_p,  g_h);
    cudaGetSymbolAddress((void**)&h2_p, g_h2);

    const int TB = 256;
    const int node_blocks = (N_NODES + TB - 1) / TB;
    const int edge_blocks = (N_EDGES + TB - 1) / TB;
    const int gemm_blocks = (N_NODES + 63) / 64;
    const int agg_blocks  = (N_NODES * 16 + TB - 1) / TB;

    // prolog: degrees + CSR (4 launches; single-pass scan)
    zero_kernel<<<node_blocks, TB>>>();
    hist_kernel<<<edge_blocks, TB>>>(row, col);
    scan_lookback_kernel<<<SCAN_NB, 256>>>();
    build_kernel<<<edge_blocks, TB>>>(row, col);

    // layer 1
    dual_gemm_kernel<<<gemm_blocks, 256>>>(x, W_nb1, W_in1, b1, t_p, h_p);
    agg_kernel<<<agg_blocks, TB>>>(t_p, h_p);

    // layer 2
    dual_gemm_kernel<<<gemm_blocks, 256>>>(h_p, W_nb2, W_in2, b2, t_p, h2_p);
    agg_kernel<<<agg_blocks, TB>>>(t_p, h2_p);

    // output projection
    out_gemm_kernel<<<gemm_blocks, 128>>>(h2_p, W_out, b_out, out);
}

// round 9
// speedup vs baseline: 1.6902x; 1.6902x over previous
#include <cuda_runtime.h>
#include <cuda_fp16.h>

#define N_NODES 50000
#define N_EDGES 800000
#define SCAN_NB ((N_NODES + 255) / 256)   // 196 blocks

// ---- scratch (allocation-free: __device__ globals) ----
__device__ float  g_deg  [N_NODES];
__device__ float  g_dinv [N_NODES];
__device__ int    g_cnt  [N_NODES];
__device__ int    g_off  [N_NODES + 1];
__device__ int    g_cur  [N_NODES];
__device__ int    g_bsum [SCAN_NB];
__device__ int    g_srow [N_EDGES];
__device__ float  g_snorm[N_EDGES];
__device__ __half g_t  [N_NODES * 64];    // neighbor transform, fp16 storage
__device__ float  g_h  [N_NODES * 64];
__device__ float  g_h2 [N_NODES * 64];

// ---------------------------------------------------------------------------
__global__ void zero_kernel() {
    int n = blockIdx.x * blockDim.x + threadIdx.x;
    if (n < N_NODES) { g_deg[n] = 0.0f; g_cnt[n] = 0; }
}

__global__ void hist_kernel(const int* __restrict__ row, const int* __restrict__ col) {
    int e = blockIdx.x * blockDim.x + threadIdx.x;
    if (e < N_EDGES) {
        atomicAdd(&g_deg[row[e]], 1.0f);
        atomicAdd(&g_cnt[col[e]], 1);
    }
}

// ---------------------------------------------------------------------------
__device__ __forceinline__ int block_excl_scan_256(int v, int tid) {
    int lane = tid & 31, wid = tid >> 5;
    int x = v;
#pragma unroll
    for (int d = 1; d < 32; d <<= 1) {
        int y = __shfl_up_sync(0xFFFFFFFFu, x, d);
        if (lane >= d) x += y;
    }
    __shared__ int wsum[8];
    if (lane == 31) wsum[wid] = x;
    __syncthreads();
    if (wid == 0) {
        int w = (lane < 8) ? wsum[lane] : 0;
#pragma unroll
        for (int d = 1; d < 8; d <<= 1) {
            int y = __shfl_up_sync(0xFFFFFFFFu, w, d);
            if (lane >= d) w += y;
        }
        if (lane < 8) wsum[lane] = w;
    }
    __syncthreads();
    int incl = x + (wid > 0 ? wsum[wid - 1] : 0);
    return incl - v;
}

__global__ void scan1_kernel() {
    int i = blockIdx.x * 256 + threadIdx.x;
    int v = (i < N_NODES) ? g_cnt[i] : 0;
    int excl = block_excl_scan_256(v, threadIdx.x);
    if (i < N_NODES) g_off[i] = excl;
    if (threadIdx.x == 255) g_bsum[blockIdx.x] = excl + v;
}

__global__ void scan2_kernel() {
    int t = threadIdx.x;
    int v = (t < SCAN_NB) ? g_bsum[t] : 0;
    int excl = block_excl_scan_256(v, t);
    if (t < SCAN_NB) g_bsum[t] = excl;
}

__global__ void scan3_kernel() {
    int i = blockIdx.x * 256 + threadIdx.x;
    if (i < N_NODES) {
        int o = g_off[i] + g_bsum[blockIdx.x];
        g_off[i] = o;
        g_cur[i] = o;
        float d = g_deg[i];
        g_dinv[i] = (d > 0.0f) ? rsqrtf(d) : 0.0f;
    }
    if (i == 0) g_off[N_NODES] = N_EDGES;
}

__global__ void build_kernel(const int* __restrict__ row, const int* __restrict__ col) {
    int e = blockIdx.x * blockDim.x + threadIdx.x;
    if (e < N_EDGES) {
        int r = row[e], c = col[e];
        int p = atomicAdd(&g_cur[c], 1);
        g_srow[p]  = r;
        g_snorm[p] = g_dinv[r] * g_dinv[c];
    }
}

// ---------------------------------------------------------------------------
// Fused dual GEMM: T(fp16) = A @ Wa,  H(fp32) = A @ Wb + bias
__global__ void dual_gemm_kernel(const float* __restrict__ A,
                                 const float* __restrict__ Wa,
                                 const float* __restrict__ Wb,
                                 const float* __restrict__ bias,
                                 __half* __restrict__ T,
                                 float* __restrict__ H) {
    __shared__ float xs[64][65];
    const int tid  = threadIdx.x;
    const int row0 = blockIdx.x * 64;

    for (int i = tid; i < 64 * 16; i += 256) {
        int r = i >> 4, c4 = i & 15;
        float4 v = make_float4(0.f, 0.f, 0.f, 0.f);
        int gr = row0 + r;
        if (gr < N_NODES) v = __ldg(reinterpret_cast<const float4*>(A) + gr * 16 + c4);
        xs[r][c4 * 4 + 0] = v.x; xs[r][c4 * 4 + 1] = v.y;
        xs[r][c4 * 4 + 2] = v.z; xs[r][c4 * 4 + 3] = v.w;
    }
    __syncthreads();

    const int tr = tid >> 4, tc = tid & 15;
    const int r0 = tr * 4, c0 = tc * 4;

    float accA[4][4], accB[4][4];
#pragma unroll
    for (int i = 0; i < 4; i++)
#pragma unroll
        for (int j = 0; j < 4; j++) { accA[i][j] = 0.f; accB[i][j] = 0.f; }

#pragma unroll 8
    for (int k = 0; k < 64; k++) {
        float4 wa = __ldg(reinterpret_cast<const float4*>(Wa + k * 64 + c0));
        float4 wb = __ldg(reinterpret_cast<const float4*>(Wb + k * 64 + c0));
        float x0 = xs[r0 + 0][k];
        float x1 = xs[r0 + 1][k];
        float x2 = xs[r0 + 2][k];
        float x3 = xs[r0 + 3][k];
        accA[0][0] = fmaf(x0, wa.x, accA[0][0]); accA[0][1] = fmaf(x0, wa.y, accA[0][1]);
        accA[0][2] = fmaf(x0, wa.z, accA[0][2]); accA[0][3] = fmaf(x0, wa.w, accA[0][3]);
        accA[1][0] = fmaf(x1, wa.x, accA[1][0]); accA[1][1] = fmaf(x1, wa.y, accA[1][1]);
        accA[1][2] = fmaf(x1, wa.z, accA[1][2]); accA[1][3] = fmaf(x1, wa.w, accA[1][3]);
        accA[2][0] = fmaf(x2, wa.x, accA[2][0]); accA[2][1] = fmaf(x2, wa.y, accA[2][1]);
        accA[2][2] = fmaf(x2, wa.z, accA[2][2]); accA[2][3] = fmaf(x2, wa.w, accA[2][3]);
        accA[3][0] = fmaf(x3, wa.x, accA[3][0]); accA[3][1] = fmaf(x3, wa.y, accA[3][1]);
        accA[3][2] = fmaf(x3, wa.z, accA[3][2]); accA[3][3] = fmaf(x3, wa.w, accA[3][3]);
        accB[0][0] = fmaf(x0, wb.x, accB[0][0]); accB[0][1] = fmaf(x0, wb.y, accB[0][1]);
        accB[0][2] = fmaf(x0, wb.z, accB[0][2]); accB[0][3] = fmaf(x0, wb.w, accB[0][3]);
        accB[1][0] = fmaf(x1, wb.x, accB[1][0]); accB[1][1] = fmaf(x1, wb.y, accB[1][1]);
        accB[1][2] = fmaf(x1, wb.z, accB[1][2]); accB[1][3] = fmaf(x1, wb.w, accB[1][3]);
        accB[2][0] = fmaf(x2, wb.x, accB[2][0]); accB[2][1] = fmaf(x2, wb.y, accB[2][1]);
        accB[2][2] = fmaf(x2, wb.z, accB[2][2]); accB[2][3] = fmaf(x2, wb.w, accB[2][3]);
        accB[3][0] = fmaf(x3, wb.x, accB[3][0]); accB[3][1] = fmaf(x3, wb.y, accB[3][1]);
        accB[3][2] = fmaf(x3, wb.z, accB[3][2]); accB[3][3] = fmaf(x3, wb.w, accB[3][3]);
    }

    float4 bv = __ldg(reinterpret_cast<const float4*>(bias + c0));

#pragma unroll
    for (int i = 0; i < 4; i++) {
        int gr = row0 + r0 + i;
        if (gr < N_NODES) {
            // T row chunk as 4 halves = one uint2 store
            __half2 t01 = __floats2half2_rn(accA[i][0], accA[i][1]);
            __half2 t23 = __floats2half2_rn(accA[i][2], accA[i][3]);
            uint2 tp;
            tp.x = *reinterpret_cast<unsigned*>(&t01);
            tp.y = *reinterpret_cast<unsigned*>(&t23);
            *reinterpret_cast<uint2*>(reinterpret_cast<char*>(T) + (gr * 64 + c0) * 2) = tp;

            float4 ob = make_float4(accB[i][0] + bv.x, accB[i][1] + bv.y,
                                    accB[i][2] + bv.z, accB[i][3] + bv.w);
            *reinterpret_cast<float4*>(H + gr * 64 + c0) = ob;
        }
    }
}

// Output GEMM: C[N,32] = A[N,64] @ W[64,32] + b. 64-row tile, 128 threads.
__global__ void out_gemm_kernel(const float* __restrict__ A,
                                const float* __restrict__ W,
                                const float* __restrict__ bias,
                                float* __restrict__ C) {
    __shared__ float xs[64][65];
    const int tid  = threadIdx.x;
    const int row0 = blockIdx.x * 64;

    for (int i = tid; i < 64 * 16; i += 128) {
        int r = i >> 4, c4 = i & 15;
        float4 v = make_float4(0.f, 0.f, 0.f, 0.f);
        int gr = row0 + r;
        if (gr < N_NODES) v = __ldg(reinterpret_cast<const float4*>(A) + gr * 16 + c4);
        xs[r][c4 * 4 + 0] = v.x; xs[r][c4 * 4 + 1] = v.y;
        xs[r][c4 * 4 + 2] = v.z; xs[r][c4 * 4 + 3] = v.w;
    }
    __syncthreads();

    const int tr = tid >> 3, tc = tid & 7;
    const int r0 = tr * 4, c0 = tc * 4;

    float acc[4][4];
#pragma unroll
    for (int i = 0; i < 4; i++)
#pragma unroll
        for (int j = 0; j < 4; j++) acc[i][j] = 0.f;

#pragma unroll 8
    for (int k = 0; k < 64; k++) {
        float4 wv = __ldg(reinterpret_cast<const float4*>(W + k * 32 + c0));
        float x0 = xs[r0 + 0][k];
        float x1 = xs[r0 + 1][k];
        float x2 = xs[r0 + 2][k];
        float x3 = xs[r0 + 3][k];
        acc[0][0] = fmaf(x0, wv.x, acc[0][0]); acc[0][1] = fmaf(x0, wv.y, acc[0][1]);
        acc[0][2] = fmaf(x0, wv.z, acc[0][2]); acc[0][3] = fmaf(x0, wv.w, acc[0][3]);
        acc[1][0] = fmaf(x1, wv.x, acc[1][0]); acc[1][1] = fmaf(x1, wv.y, acc[1][1]);
        acc[1][2] = fmaf(x1, wv.z, acc[1][2]); acc[1][3] = fmaf(x1, wv.w, acc[1][3]);
        acc[2][0] = fmaf(x2, wv.x, acc[2][0]); acc[2][1] = fmaf(x2, wv.y, acc[2][1]);
        acc[2][2] = fmaf(x2, wv.z, acc[2][2]); acc[2][3] = fmaf(x2, wv.w, acc[2][3]);
        acc[3][0] = fmaf(x3, wv.x, acc[3][0]); acc[3][1] = fmaf(x3, wv.y, acc[3][1]);
        acc[3][2] = fmaf(x3, wv.z, acc[3][2]); acc[3][3] = fmaf(x3, wv.w, acc[3][3]);
    }

    float4 bv = __ldg(reinterpret_cast<const float4*>(bias + c0));
#pragma unroll
    for (int i = 0; i < 4; i++) {
        int gr = row0 + r0 + i;
        if (gr < N_NODES) {
            float4 o = make_float4(acc[i][0] + bv.x, acc[i][1] + bv.y,
                                   acc[i][2] + bv.z, acc[i][3] + bv.w);
            *reinterpret_cast<float4*>(C + gr * 32 + c0) = o;
        }
    }
}

// ---------------------------------------------------------------------------
// CSR aggregation + ReLU: 16 threads per node; t rows are fp16, so each
// thread's 4-column chunk is one 8-byte gather (half the R3 bytes).
__global__ void agg_kernel(const __half* __restrict__ t, float* __restrict__ h) {
    int gid  = blockIdx.x * blockDim.x + threadIdx.x;
    int node = gid >> 4;
    if (node >= N_NODES) return;
    int c4 = gid & 15;

    int s = g_off[node];
    int e = g_off[node + 1];

    float4 acc = *reinterpret_cast<const float4*>(h + node * 64 + c4 * 4);

    for (int j = s; j < e; j++) {
        int   r  = __ldg(&g_srow[j]);
        float nv = __ldg(&g_snorm[j]);
        uint2 hp = __ldg(reinterpret_cast<const uint2*>(
                       reinterpret_cast<const char*>(t) + (r * 64 + c4 * 4) * 2));
        __half2 h01 = *reinterpret_cast<__half2*>(&hp.x);
        __half2 h23 = *reinterpret_cast<__half2*>(&hp.y);
        float2 v01 = __half22float2(h01);
        float2 v23 = __half22float2(h23);
        acc.x = fmaf(v01.x, nv, acc.x);
        acc.y = fmaf(v01.y, nv, acc.y);
        acc.z = fmaf(v23.x, nv, acc.z);
        acc.w = fmaf(v23.y, nv, acc.w);
    }

    acc.x = fmaxf(acc.x, 0.f);
    acc.y = fmaxf(acc.y, 0.f);
    acc.z = fmaxf(acc.z, 0.f);
    acc.w = fmaxf(acc.w, 0.f);
    *reinterpret_cast<float4*>(h + node * 64 + c4 * 4) = acc;
}

// ---------------------------------------------------------------------------
extern "C" void kernel_launch(void* const* d_in, const int* in_sizes, int n_in,
                              void* d_out, int out_size) {
    const float* x      = (const float*)d_in[0];
    const int*   ei     = (const int*)d_in[1];
    const int*   row    = ei;
    const int*   col    = ei + N_EDGES;
    const float* W_in1  = (const float*)d_in[2];
    const float* W_nb1  = (const float*)d_in[3];
    const float* b1     = (const float*)d_in[4];
    const float* W_in2  = (const float*)d_in[5];
    const float* W_nb2  = (const float*)d_in[6];
    const float* b2     = (const float*)d_in[7];
    const float* W_out  = (const float*)d_in[8];
    const float* b_out  = (const float*)d_in[9];
    float*       out    = (float*)d_out;

    __half* t_p;
    float *h_p, *h2_p;
    cudaGetSymbolAddress((void**)&t_p,  g_t);
    cudaGetSymbolAddress((void**)&h_p,  g_h);
    cudaGetSymbolAddress((void**)&h2_p, g_h2);

    const int TB = 256;
    const int node_blocks = (N_NODES + TB - 1) / TB;
    const int edge_blocks = (N_EDGES + TB - 1) / TB;
    const int gemm_blocks = (N_NODES + 63) / 64;
    const int agg_blocks  = (N_NODES * 16 + TB - 1) / TB;

    // prolog (R3-proven 3-pass scan)
    zero_kernel<<<node_blocks, TB>>>();
    hist_kernel<<<edge_blocks, TB>>>(row, col);
    scan1_kernel<<<SCAN_NB, 256>>>();
    scan2_kernel<<<1, 256>>>();
    scan3_kernel<<<SCAN_NB, 256>>>();
    build_kernel<<<edge_blocks, TB>>>(row, col);

    // layer 1
    dual_gemm_kernel<<<gemm_blocks, 256>>>(x, W_nb1, W_in1, b1, t_p, h_p);
    agg_kernel<<<agg_blocks, TB>>>(t_p, h_p);

    // layer 2
    dual_gemm_kernel<<<gemm_blocks, 256>>>(h_p, W_nb2, W_in2, b2, t_p, h2_p);
    agg_kernel<<<agg_blocks, TB>>>(t_p, h2_p);

    // output projection
    out_gemm_kernel<<<gemm_blocks, 128>>>(h2_p, W_out, b_out, out);
}